// round 14
// baseline (speedup 1.0000x reference)
#include <cuda_runtime.h>
#include <cuda_bf16.h>
#include <math.h>
#include <stdint.h>

#define BB 32
#define MM 600
#define HH 256
#define TT 4
#define H2 512
#define H4 1024
#define H5 1280
#define HP 4096
#define MTOT (BB*MM)      /* 19200 */
#define K1A 1536          /* precompute GEMM K = 3*512 */
#define K2A 768           /* maxout GEMM K = 3*256 */

// ---------------- device scratch ----------------
__device__ float g_CU_s[(size_t)MTOT*HP];
__device__ float g_CU_e[(size_t)MTOT*HP];
__device__ __nv_bfloat16 g_A3[(size_t)MTOT*K1A];
__device__ __nv_bfloat16 g_B3s[(size_t)HP*K1A];
__device__ __nv_bfloat16 g_B3e[(size_t)HP*K1A];
__device__ __nv_bfloat16 g_W23s[(size_t)HP*K2A];
__device__ __nv_bfloat16 g_W23e[(size_t)HP*K2A];
__device__ __nv_bfloat16 g_m3[(size_t)MTOT*K2A];
__device__ float g_m1[(size_t)MTOT*HH];
__device__ float g_m2[(size_t)MTOT*HH];
__device__ float g_h[2*BB*HH];
__device__ float g_c[2*BB*HH];
__device__ float g_r[BB*HH];
__device__ float g_add[BB*HP];
__device__ float g_alpha[BB*MM];          // masked entries never written: stay 0
__device__ int   g_si[BB], g_ei[BB], g_ms[BB], g_me[BB];
__device__ int   g_len[BB];
__device__ int   g_off[BB+1];
__device__ int   g_rowb[MTOT], g_rowm[MTOT];
__device__ float g_lterm_s[TT*BB], g_lterm_e[TT*BB];
__device__ int   g_res_s[TT*BB], g_res_e[TT*BB], g_resms[TT*BB], g_resme[TT*BB];

__device__ __forceinline__ float sigm(float x) { return 1.0f / (1.0f + expf(-x)); }

__device__ __forceinline__ uint32_t smem_u32(const void* p) {
    uint32_t a;
    asm("{ .reg .u64 t; cvta.to.shared.u64 t, %1; cvt.u32.u64 %0, t; }" : "=r"(a) : "l"(p));
    return a;
}
__device__ __forceinline__ void cp16(uint32_t dst, const void* src) {
    asm volatile("cp.async.cg.shared.global [%0], [%1], 16;" :: "r"(dst), "l"(src) : "memory");
}
__device__ __forceinline__ void ldm_x4(uint32_t* r, uint32_t addr) {
    asm volatile("ldmatrix.sync.aligned.m8n8.x4.shared.b16 {%0,%1,%2,%3}, [%4];"
        : "=r"(r[0]), "=r"(r[1]), "=r"(r[2]), "=r"(r[3]) : "r"(addr));
}
__device__ __forceinline__ void ldm_x2(uint32_t* r, uint32_t addr) {
    asm volatile("ldmatrix.sync.aligned.m8n8.x2.shared.b16 {%0,%1}, [%2];"
        : "=r"(r[0]), "=r"(r[1]) : "r"(addr));
}
__device__ __forceinline__ void mma16816(float* c, const uint32_t* a, const uint32_t* b) {
    asm volatile("mma.sync.aligned.m16n8k16.row.col.f32.bf16.bf16.f32 "
        "{%0,%1,%2,%3}, {%4,%5,%6,%7}, {%8,%9}, {%0,%1,%2,%3};"
        : "+f"(c[0]), "+f"(c[1]), "+f"(c[2]), "+f"(c[3])
        : "r"(a[0]), "r"(a[1]), "r"(a[2]), "r"(a[3]), "r"(b[0]), "r"(b[1]));
}

// ---------------- init ----------------
__global__ void __launch_bounds__(256) init_kernel(const int* __restrict__ dmask) {
    int b = blockIdx.x, tid = threadIdx.x;
    g_h[b*HH + tid] = 0.f;
    g_c[b*HH + tid] = 0.f;
    __shared__ int red[256];
    int s = 0;
    for (int m = tid; m < MM; m += 256) s += dmask[b*MM + m];
    red[tid] = s; __syncthreads();
    for (int st = 128; st; st >>= 1) { if (tid < st) red[tid] += red[tid + st]; __syncthreads(); }
    if (tid == 0) { g_si[b] = 0; g_ei[b] = red[0] - 1; g_len[b] = red[0]; g_ms[b] = 0; g_me[b] = 0; }
}

__global__ void prefix_kernel() {
    int t = threadIdx.x;
    int v = g_len[t];
    int x = v;
    #pragma unroll
    for (int o = 1; o < 32; o <<= 1) {
        int y = __shfl_up_sync(0xffffffffu, x, o);
        if (t >= o) x += y;
    }
    g_off[t] = x - v;
    if (t == 31) g_off[32] = x;
}

__global__ void __launch_bounds__(256) map_kernel() {
    int idx = blockIdx.x * 256 + threadIdx.x;
    int b = idx / MM, m = idx - b * MM;
    if (m < g_len[b]) {
        int cr = g_off[b] + m;
        g_rowb[cr] = b;
        g_rowm[cr] = m;
    }
}

// ---------------- bf16 split conversions ----------------
__device__ __forceinline__ void split2(float x, __nv_bfloat16& hi, __nv_bfloat16& lo) {
    hi = __float2bfloat16(x);
    lo = __float2bfloat16(x - __bfloat162float(hi));
}

__global__ void __launch_bounds__(256) convA3_kernel(const float* __restrict__ U) {
    int idx = blockIdx.x * 256 + threadIdx.x;
    int i = idx >> 9, c = idx & 511;
    int b = i / MM, m = i - b * MM;
    if (m >= g_len[b]) return;
    int crow = g_off[b] + m;
    __nv_bfloat16 hi, lo; split2(U[idx], hi, lo);
    size_t base = (size_t)crow * K1A;
    g_A3[base + c] = hi; g_A3[base + 512 + c] = lo; g_A3[base + 1024 + c] = hi;
}
__global__ void __launch_bounds__(256) convB3_kernel(const float* __restrict__ W, int which) {
    __nv_bfloat16* B3 = which ? g_B3e : g_B3s;
    int idx = blockIdx.x * 256 + threadIdx.x;
    int j = idx >> 9, c = idx & 511;
    __nv_bfloat16 hi, lo; split2(W[(size_t)j * 768 + c], hi, lo);
    size_t base = (size_t)j * K1A;
    B3[base + c] = hi; B3[base + 512 + c] = hi; B3[base + 1024 + c] = lo;
}
__global__ void __launch_bounds__(256) convW23_kernel(const float* __restrict__ W2, int which) {
    __nv_bfloat16* W23 = which ? g_W23e : g_W23s;
    int idx = blockIdx.x * 256 + threadIdx.x;
    int j = idx >> 8, c = idx & 255;
    __nv_bfloat16 hi, lo; split2(W2[(size_t)j * 256 + c], hi, lo);
    size_t base = (size_t)j * K2A;
    W23[base + c] = hi; W23[base + 256 + c] = hi; W23[base + 512 + c] = lo;
}

// ---------------- HMMA GEMM (R5 body), compact rows, skip stripes >= R ----------------
// mode 0: raw fp32 store. mode 1: bias + maxpool16 -> Cout[rows, 256].
__global__ void __launch_bounds__(256) gemm_hmma_kernel(
    const __nv_bfloat16* __restrict__ A, const __nv_bfloat16* __restrict__ Bw,
    float* __restrict__ Cout, const float* __restrict__ bias, int Ktot, int mode)
{
    int m0 = blockIdx.x * 128, n0 = blockIdx.y * 128;
    if (m0 >= g_off[BB]) return;

    __shared__ __align__(16) __nv_bfloat16 As[2][128][40];
    __shared__ __align__(16) __nv_bfloat16 Bs[2][128][40];
    int tid = threadIdx.x, lane = tid & 31, wid = tid >> 5;
    int wm = wid >> 2, wn = wid & 3;

    const int STG = 128 * 40 * 2;
    uint32_t sA = smem_u32(&As[0][0][0]);
    uint32_t sB = smem_u32(&Bs[0][0][0]);

    float acc[4][4][4];
    #pragma unroll
    for (int i = 0; i < 4; i++)
        #pragma unroll
        for (int j = 0; j < 4; j++)
            #pragma unroll
            for (int q = 0; q < 4; q++) acc[i][j][q] = 0.f;

    auto load_stage = [&](int c, int buf) {
        int kc = c * 32;
        #pragma unroll
        for (int i = 0; i < 2; i++) {
            int f = tid + i * 256;
            int r = f >> 2, q = f & 3;
            cp16(sA + buf * STG + r * 80 + q * 16, A + (size_t)(m0 + r) * Ktot + kc + q * 8);
        }
        #pragma unroll
        for (int i = 0; i < 2; i++) {
            int f = tid + i * 256;
            int r = f >> 2, q = f & 3;
            cp16(sB + buf * STG + r * 80 + q * 16, Bw + (size_t)(n0 + r) * Ktot + kc + q * 8);
        }
        asm volatile("cp.async.commit_group;" ::: "memory");
    };

    auto compute = [&](int buf) {
        #pragma unroll
        for (int ks = 0; ks < 2; ks++) {
            uint32_t a[4][4], b[4][2];
            #pragma unroll
            for (int mi = 0; mi < 4; mi++) {
                uint32_t addr = sA + buf * STG
                    + (wm * 64 + mi * 16 + (lane & 15)) * 80 + (ks * 16 + (lane >> 4) * 8) * 2;
                ldm_x4(a[mi], addr);
            }
            #pragma unroll
            for (int ni = 0; ni < 4; ni++) {
                uint32_t addr = sB + buf * STG
                    + (wn * 32 + ni * 8 + (lane & 7)) * 80 + (ks * 16 + ((lane >> 3) & 1) * 8) * 2;
                ldm_x2(b[ni], addr);
            }
            #pragma unroll
            for (int mi = 0; mi < 4; mi++)
                #pragma unroll
                for (int ni = 0; ni < 4; ni++)
                    mma16816(acc[mi][ni], a[mi], b[ni]);
        }
    };

    int NC = Ktot >> 5;
    load_stage(0, 0);
    for (int c = 0; c < NC; c++) {
        if (c + 1 < NC) {
            load_stage(c + 1, (c + 1) & 1);
            asm volatile("cp.async.wait_group 1;" ::: "memory");
        } else {
            asm volatile("cp.async.wait_group 0;" ::: "memory");
        }
        __syncthreads();
        compute(c & 1);
        __syncthreads();
    }

    int gr = lane >> 2, q = lane & 3;
    if (mode == 0) {
        #pragma unroll
        for (int mi = 0; mi < 4; mi++) {
            int row = m0 + wm * 64 + mi * 16 + gr;
            float* d0 = Cout + (size_t)row * HP + n0 + wn * 32;
            float* d1 = Cout + (size_t)(row + 8) * HP + n0 + wn * 32;
            #pragma unroll
            for (int ni = 0; ni < 4; ni++) {
                int colq = ni * 8 + q * 2;
                *(float2*)(d0 + colq) = make_float2(acc[mi][ni][0], acc[mi][ni][1]);
                *(float2*)(d1 + colq) = make_float2(acc[mi][ni][2], acc[mi][ni][3]);
            }
        }
    } else {
        float bv[2][2][2];
        #pragma unroll
        for (int g = 0; g < 2; g++)
            #pragma unroll
            for (int f2 = 0; f2 < 2; f2++)
                #pragma unroll
                for (int j = 0; j < 2; j++)
                    bv[g][f2][j] = __ldg(bias + n0 + wn * 32 + g * 16 + f2 * 8 + q * 2 + j);
        #pragma unroll
        for (int mi = 0; mi < 4; mi++) {
            int row = m0 + wm * 64 + mi * 16 + gr;
            #pragma unroll
            for (int g = 0; g < 2; g++) {
                float lo = -3.4e38f, hi = -3.4e38f;
                #pragma unroll
                for (int f2 = 0; f2 < 2; f2++) {
                    lo = fmaxf(lo, fmaxf(acc[mi][2*g + f2][0] + bv[g][f2][0],
                                         acc[mi][2*g + f2][1] + bv[g][f2][1]));
                    hi = fmaxf(hi, fmaxf(acc[mi][2*g + f2][2] + bv[g][f2][0],
                                         acc[mi][2*g + f2][3] + bv[g][f2][1]));
                }
                lo = fmaxf(lo, __shfl_xor_sync(0xffffffffu, lo, 1));
                lo = fmaxf(lo, __shfl_xor_sync(0xffffffffu, lo, 2));
                hi = fmaxf(hi, __shfl_xor_sync(0xffffffffu, hi, 1));
                hi = fmaxf(hi, __shfl_xor_sync(0xffffffffu, hi, 2));
                if (q == 0) {
                    int h = ((n0 + wn * 32) >> 4) + g;
                    Cout[(size_t)row * HH + h] = lo;
                    Cout[(size_t)(row + 8) * HH + h] = hi;
                }
            }
        }
    }
}

// ---------------- LSTM (warp per (j,b); 8 warps/block share j -> weight rows L1-broadcast) ----------------
__global__ void __launch_bounds__(256) lstm_kernel(const float* __restrict__ U,
        const float* __restrict__ Wih, const float* __restrict__ Whh,
        const float* __restrict__ bih, const float* __restrict__ bhh, int rb) {
    int w = blockIdx.x * 8 + (threadIdx.x >> 5);
    int j = w >> 5, b = w & 31, l = threadIdx.x & 31;   // 8 warps in a block: same j, 8 batches
    const float4* us = (const float4*)(U + (size_t)(b * MM + g_si[b]) * H2);
    const float4* ue = (const float4*)(U + (size_t)(b * MM + g_ei[b]) * H2);
    const float4* hb = (const float4*)(g_h + rb * (BB * HH) + b * HH);
    float acc[4] = {0.f, 0.f, 0.f, 0.f};
    #pragma unroll
    for (int i = 0; i < 8; i++) {
        int k4 = l + 32 * i;
        float4 x = (k4 < 128) ? us[k4] : ue[k4 - 128];
        #pragma unroll
        for (int qg = 0; qg < 4; qg++) {
            float4 ww = ((const float4*)(Wih + (size_t)(qg * HH + j) * H4))[k4];
            acc[qg] += x.x * ww.x + x.y * ww.y + x.z * ww.z + x.w * ww.w;
        }
    }
    #pragma unroll
    for (int i = 0; i < 2; i++) {
        int k4 = l + 32 * i;
        float4 x = hb[k4];
        #pragma unroll
        for (int qg = 0; qg < 4; qg++) {
            float4 ww = ((const float4*)(Whh + (size_t)(qg * HH + j) * HH))[k4];
            acc[qg] += x.x * ww.x + x.y * ww.y + x.z * ww.z + x.w * ww.w;
        }
    }
    #pragma unroll
    for (int qg = 0; qg < 4; qg++)
        #pragma unroll
        for (int o = 16; o; o >>= 1) acc[qg] += __shfl_xor_sync(0xffffffffu, acc[qg], o);
    if (l == 0) {
        float gi = acc[0] + bih[j]        + bhh[j];
        float gf = acc[1] + bih[HH + j]   + bhh[HH + j];
        float gg = acc[2] + bih[2*HH + j] + bhh[2*HH + j];
        float go = acc[3] + bih[3*HH + j] + bhh[3*HH + j];
        float co = g_c[rb * (BB*HH) + b*HH + j];
        float cn = sigm(gf) * co + sigm(gi) * tanhf(gg);
        int wb = 1 - rb;
        g_c[wb * (BB*HH) + b*HH + j] = cn;
        g_h[wb * (BB*HH) + b*HH + j] = sigm(go) * tanhf(cn);
    }
}

// ---------------- r = tanh([h,u_s,u_e] @ Wlin^T)  (warp per (j,b); blocks share j) ----------------
__global__ void __launch_bounds__(256) r_kernel(const float* __restrict__ U,
                                                const float* __restrict__ Wlin, int hbuf) {
    int w = blockIdx.x * 8 + (threadIdx.x >> 5);
    int j = w >> 5, b = w & 31, l = threadIdx.x & 31;
    const float4* hb = (const float4*)(g_h + hbuf * (BB * HH) + b * HH);
    const float4* us = (const float4*)(U + (size_t)(b * MM + g_si[b]) * H2);
    const float4* ue = (const float4*)(U + (size_t)(b * MM + g_ei[b]) * H2);
    const float4* wr = (const float4*)(Wlin + (size_t)j * H5);
    float acc = 0.f;
    #pragma unroll
    for (int i = 0; i < 10; i++) {
        int k4 = l + 32 * i;
        float4 x = (k4 < 64) ? hb[k4] : ((k4 < 192) ? us[k4 - 64] : ue[k4 - 192]);
        float4 ww = wr[k4];
        acc += x.x * ww.x + x.y * ww.y + x.z * ww.z + x.w * ww.w;
    }
    #pragma unroll
    for (int o = 16; o; o >>= 1) acc += __shfl_xor_sync(0xffffffffu, acc, o);
    if (l == 0) g_r[b * HH + j] = tanhf(acc);
}

// ---------------- addend[b][j] = b1[j] + r[b] . W1[j, 512:768] ----------------
__global__ void __launch_bounds__(256) addend_kernel(const float* __restrict__ Wm1,
                                                     const float* __restrict__ bm1) {
    __shared__ float sr[HH];
    int b = blockIdx.x, tid = threadIdx.x;
    for (int k = tid; k < HH; k += 256) sr[k] = g_r[b*HH + k];
    __syncthreads();
    int j = blockIdx.y * 256 + tid;
    const float* w = Wm1 + (size_t)j * 768 + 512;
    float acc = bm1[j];
    #pragma unroll 8
    for (int k = 0; k < HH; k += 4) {
        float4 x = *(const float4*)(sr + k);
        float4 a = *(const float4*)(w + k);
        acc += x.x * a.x + x.y * a.y + x.z * a.z + x.w * a.w;
    }
    g_add[b*HP + j] = acc;
}

// ---------------- phase1 (compact rows): m1 = maxpool16(CU + add) ----------------
__global__ void __launch_bounds__(256) phase1_kernel(int which) {
    const float* CU = which ? g_CU_e : g_CU_s;
    int R = g_off[BB];
    int crow0 = blockIdx.x * 8, tid = threadIdx.x;
    if (crow0 >= R) return;
    int j0 = tid * 16;
    #pragma unroll
    for (int rr = 0; rr < 8; rr++) {
        int crow = crow0 + rr;
        if (crow >= R) break;
        int b = g_rowb[crow];
        const float* ab = g_add + b * HP;
        const float* cu = CU + (size_t)crow * HP;
        float mx = -3.4e38f;
        #pragma unroll
        for (int qq = 0; qq < 4; qq++) {
            float4 v = *(const float4*)(cu + j0 + qq * 4);
            float4 a = __ldg((const float4*)(ab + j0 + qq * 4));
            mx = fmaxf(mx, fmaxf(fmaxf(v.x + a.x, v.y + a.y), fmaxf(v.z + a.z, v.w + a.w)));
        }
        g_m1[(size_t)crow * HH + tid] = mx;
        __nv_bfloat16 hi, lo; split2(mx, hi, lo);
        g_m3[(size_t)crow * K2A + tid] = hi;
        g_m3[(size_t)crow * K2A + 256 + tid] = lo;
        g_m3[(size_t)crow * K2A + 512 + tid] = hi;
    }
}

// ---------------- phase3 (compact rows): alpha = max_p([m1,m2] . W12[p] + b12[p]) ----------------
__global__ void __launch_bounds__(256) alpha_kernel(const float* __restrict__ W12,
                                                    const float* __restrict__ b12) {
    __shared__ float w12T[512 * 17];
    int R = g_off[BB];
    int crow0 = blockIdx.x * 8;
    if (crow0 >= R) return;
    int tid = threadIdx.x, wid = tid >> 5, l = tid & 31;
    for (int idx = tid; idx < 8192; idx += 256) {
        int p = idx >> 9, k = idx & 511;
        w12T[k * 17 + p] = W12[idx];
    }
    __syncthreads();
    int crow = crow0 + wid;
    if (crow < R) {
        float acc[16];
        #pragma unroll
        for (int p = 0; p < 16; p++) acc[p] = 0.f;
        #pragma unroll
        for (int i = 0; i < 16; i++) {
            int k = i * 32 + l;
            float a = (k < 256) ? g_m1[(size_t)crow * HH + k] : g_m2[(size_t)crow * HH + (k - 256)];
            const float* wr = w12T + k * 17;
            #pragma unroll
            for (int p = 0; p < 16; p++) acc[p] += a * wr[p];
        }
        #pragma unroll
        for (int p = 0; p < 16; p++)
            #pragma unroll
            for (int o = 16; o; o >>= 1) acc[p] += __shfl_xor_sync(0xffffffffu, acc[p], o);
        if (l == 0) {
            float mx = -3.4e38f;
            #pragma unroll
            for (int p = 0; p < 16; p++) mx = fmaxf(mx, acc[p] + __ldg(b12 + p));
            int b = g_rowb[crow], m = g_rowm[crow];
            g_alpha[b * MM + m] = mx;
        }
    }
}

// ---------------- argmax + logsumexp + state update (single global read; smem staging) ----------------
__global__ void __launch_bounds__(256) select_kernel(const int* __restrict__ dmask,
                                                     const int* __restrict__ span,
                                                     int t, int isEnd) {
    __shared__ float sval[MM];
    __shared__ float sv[256];
    __shared__ int   sidx[256];
    __shared__ float red[256];
    int b = blockIdx.x, tid = threadIdx.x;
    const float* al = g_alpha + b * MM;
    const int* dm = dmask + b * MM;

    float best = -3.4e38f; int bi = 0;
    for (int m = tid; m < MM; m += 256) {
        float v = al[m] + (dm[m] ? 0.f : -1e30f);
        sval[m] = v;
        if (v > best) { best = v; bi = m; }
    }
    sv[tid] = best; sidx[tid] = bi; __syncthreads();
    for (int s = 128; s; s >>= 1) {
        if (tid < s) {
            float ov = sv[tid + s]; int oi = sidx[tid + s];
            if (ov > sv[tid] || (ov == sv[tid] && oi < sidx[tid])) { sv[tid] = ov; sidx[tid] = oi; }
        }
        __syncthreads();
    }
    float mx = sv[0]; int amax = sidx[0];
    __syncthreads();

    float ssum = 0.f;
    for (int m = tid; m < MM; m += 256) ssum += expf(sval[m] - mx);
    red[tid] = ssum; __syncthreads();
    for (int s = 128; s; s >>= 1) { if (tid < s) red[tid] += red[tid + s]; __syncthreads(); }

    if (tid == 0) {
        float lse = mx + logf(red[0]);
        int tgt = span[b * 2 + isEnd];
        float vt = sval[tgt];
        float lterm = -(vt - lse);
        int* idxArr = isEnd ? g_ei : g_si;
        int* mArr   = isEnd ? g_me : g_ms;
        int idx = amax, mnew;
        if (t == 0) mnew = 1;
        else {
            int mo = mArr[b];
            int prev = idxArr[b] * mo;
            idx = idx * mo;
            mnew = (idx != prev) ? 1 : 0;
        }
        mArr[b] = mnew; idxArr[b] = idx;
        (isEnd ? g_res_e  : g_res_s )[t*BB + b] = idx;
        (isEnd ? g_resme  : g_resms )[t*BB + b] = mnew;
        (isEnd ? g_lterm_e: g_lterm_s)[t*BB + b] = lterm;
    }
}

// ---------------- finalize ----------------
__global__ void __launch_bounds__(64) finish_kernel(float* __restrict__ out) {
    __shared__ float Ls[TT], Le[TT];
    int tid = threadIdx.x;
    if (tid < 2 * TT) {
        int t = tid & 3;
        const float* src = (tid < TT) ? g_lterm_s : g_lterm_e;
        float s = 0.f;
        for (int b = 0; b < BB; b++) s += src[t*BB + b];
        if (tid < TT) Ls[t] = s / (float)BB; else Le[t] = s / (float)BB;
    }
    __syncthreads();
    if (tid < 32) {
        int b = tid;
        float acc = 0.f;
        for (int t = 0; t < TT; t++)
            acc += Ls[t] * (float)g_resms[t*BB + b] + Le[t] * (float)g_resme[t*BB + b];
        acc /= (float)TT;
        float tot = acc;
        #pragma unroll
        for (int o = 16; o; o >>= 1) tot += __shfl_xor_sync(0xffffffffu, tot, o);
        if (b == 0) out[0] = tot / (float)BB;
        int ps = 0, pe = 0;
        for (int t = 0; t < TT; t++) { ps += g_resms[t*BB + b]; pe += g_resme[t*BB + b]; }
        out[1 + b]  = (float)g_res_s[(ps - 1)*BB + b];
        out[33 + b] = (float)g_res_e[(pe - 1)*BB + b];
    }
}

// ---------------- host ----------------
extern "C" void kernel_launch(void* const* d_in, const int* in_sizes, int n_in,
                              void* d_out, int out_size) {
    const float* U      = (const float*)d_in[0];
    const int*   dmask  = (const int*)  d_in[1];
    const int*   span   = (const int*)  d_in[2];
    const float* Wih    = (const float*)d_in[3];
    const float* Whh    = (const float*)d_in[4];
    const float* bih    = (const float*)d_in[5];
    const float* bhh    = (const float*)d_in[6];
    const float* Ws_lin = (const float*)d_in[7];
    const float* Ws_m1  = (const float*)d_in[8];
    const float* bs_m1  = (const float*)d_in[9];
    const float* Ws_m2  = (const float*)d_in[10];
    const float* bs_m2  = (const float*)d_in[11];
    const float* Ws_m12 = (const float*)d_in[12];
    const float* bs_m12 = (const float*)d_in[13];
    const float* We_lin = (const float*)d_in[14];
    const float* We_m1  = (const float*)d_in[15];
    const float* be_m1  = (const float*)d_in[16];
    const float* We_m2  = (const float*)d_in[17];
    const float* be_m2  = (const float*)d_in[18];
    const float* We_m12 = (const float*)d_in[19];
    const float* be_m12 = (const float*)d_in[20];
    float* out = (float*)d_out;

    float *CU_s, *CU_e, *m2p;
    cudaGetSymbolAddress((void**)&CU_s, g_CU_s);
    cudaGetSymbolAddress((void**)&CU_e, g_CU_e);
    cudaGetSymbolAddress((void**)&m2p, g_m2);
    __nv_bfloat16 *A3, *B3s, *B3e, *W23s, *W23e, *m3;
    cudaGetSymbolAddress((void**)&A3, g_A3);
    cudaGetSymbolAddress((void**)&B3s, g_B3s);
    cudaGetSymbolAddress((void**)&B3e, g_B3e);
    cudaGetSymbolAddress((void**)&W23s, g_W23s);
    cudaGetSymbolAddress((void**)&W23e, g_W23e);
    cudaGetSymbolAddress((void**)&m3, g_m3);

    init_kernel<<<BB, 256>>>(dmask);
    prefix_kernel<<<1, 32>>>();
    map_kernel<<<MTOT/256, 256>>>();

    convA3_kernel<<<(MTOT*512)/256, 256>>>(U);
    convB3_kernel<<<(HP*512)/256, 256>>>(Ws_m1, 0);
    convB3_kernel<<<(HP*512)/256, 256>>>(We_m1, 1);
    convW23_kernel<<<(HP*256)/256, 256>>>(Ws_m2, 0);
    convW23_kernel<<<(HP*256)/256, 256>>>(We_m2, 1);

    dim3 ggrid(MTOT / 128, HP / 128);   // (150, 32), stripes >= R exit early
    gemm_hmma_kernel<<<ggrid, 256>>>(A3, B3s, CU_s, nullptr, K1A, 0);
    gemm_hmma_kernel<<<ggrid, 256>>>(A3, B3e, CU_e, nullptr, K1A, 0);

    for (int t = 0; t < TT; t++) {
        int rb = t & 1, wb = 1 - rb;
        lstm_kernel<<<1024, 256>>>(U, Wih, Whh, bih, bhh, rb);

        // ---- start pointer ----
        r_kernel<<<1024, 256>>>(U, Ws_lin, wb);
        addend_kernel<<<dim3(BB, 16), 256>>>(Ws_m1, bs_m1);
        phase1_kernel<<<MTOT/8, 256>>>(0);
        gemm_hmma_kernel<<<ggrid, 256>>>(m3, W23s, m2p, bs_m2, K2A, 1);
        alpha_kernel<<<MTOT/8, 256>>>(Ws_m12, bs_m12);
        select_kernel<<<BB, 256>>>(dmask, span, t, 0);

        // ---- end pointer (updated s_i, pre-update e_i) ----
        r_kernel<<<1024, 256>>>(U, We_lin, wb);
        addend_kernel<<<dim3(BB, 16), 256>>>(We_m1, be_m1);
        phase1_kernel<<<MTOT/8, 256>>>(1);
        gemm_hmma_kernel<<<ggrid, 256>>>(m3, W23e, m2p, be_m2, K2A, 1);
        alpha_kernel<<<MTOT/8, 256>>>(We_m12, be_m12);
        select_kernel<<<BB, 256>>>(dmask, span, t, 1);
    }

    finish_kernel<<<1, 64>>>(out);
}

// round 15
// speedup vs baseline: 1.0057x; 1.0057x over previous
#include <cuda_runtime.h>
#include <cuda_bf16.h>
#include <math.h>
#include <stdint.h>

#define BB 32
#define MM 600
#define HH 256
#define TT 4
#define H2 512
#define H4 1024
#define H5 1280
#define HP 4096
#define MTOT (BB*MM)      /* 19200 */
#define K1A 1536          /* precompute GEMM K = 3*512 */
#define K2A 768           /* maxout GEMM K = 3*256 */

// ---------------- device scratch ----------------
__device__ float g_CU_s[(size_t)MTOT*HP];
__device__ float g_CU_e[(size_t)MTOT*HP];
__device__ __nv_bfloat16 g_A3[(size_t)MTOT*K1A];
__device__ __nv_bfloat16 g_B3s[(size_t)HP*K1A];
__device__ __nv_bfloat16 g_B3e[(size_t)HP*K1A];
__device__ __nv_bfloat16 g_W23s[(size_t)HP*K2A];
__device__ __nv_bfloat16 g_W23e[(size_t)HP*K2A];
__device__ __nv_bfloat16 g_m3[(size_t)MTOT*K2A];
__device__ float g_m1[(size_t)MTOT*HH];
__device__ float g_m2[(size_t)MTOT*HH];
__device__ float g_h[2*BB*HH];
__device__ float g_c[2*BB*HH];
__device__ float g_r[BB*HH];
__device__ float g_add[BB*HP];
__device__ float g_alpha[BB*MM];          // masked entries never written: stay 0
__device__ int   g_si[BB], g_ei[BB], g_ms[BB], g_me[BB];
__device__ int   g_len[BB];
__device__ int   g_off[BB+1];
__device__ int   g_rowb[MTOT], g_rowm[MTOT];
__device__ float g_lterm_s[TT*BB], g_lterm_e[TT*BB];
__device__ int   g_res_s[TT*BB], g_res_e[TT*BB], g_resms[TT*BB], g_resme[TT*BB];

__device__ __forceinline__ float sigm(float x) { return 1.0f / (1.0f + expf(-x)); }

__device__ __forceinline__ uint32_t smem_u32(const void* p) {
    uint32_t a;
    asm("{ .reg .u64 t; cvta.to.shared.u64 t, %1; cvt.u32.u64 %0, t; }" : "=r"(a) : "l"(p));
    return a;
}
__device__ __forceinline__ void cp16(uint32_t dst, const void* src) {
    asm volatile("cp.async.cg.shared.global [%0], [%1], 16;" :: "r"(dst), "l"(src) : "memory");
}
__device__ __forceinline__ void ldm_x4(uint32_t* r, uint32_t addr) {
    asm volatile("ldmatrix.sync.aligned.m8n8.x4.shared.b16 {%0,%1,%2,%3}, [%4];"
        : "=r"(r[0]), "=r"(r[1]), "=r"(r[2]), "=r"(r[3]) : "r"(addr));
}
__device__ __forceinline__ void ldm_x2(uint32_t* r, uint32_t addr) {
    asm volatile("ldmatrix.sync.aligned.m8n8.x2.shared.b16 {%0,%1}, [%2];"
        : "=r"(r[0]), "=r"(r[1]) : "r"(addr));
}
__device__ __forceinline__ void mma16816(float* c, const uint32_t* a, const uint32_t* b) {
    asm volatile("mma.sync.aligned.m16n8k16.row.col.f32.bf16.bf16.f32 "
        "{%0,%1,%2,%3}, {%4,%5,%6,%7}, {%8,%9}, {%0,%1,%2,%3};"
        : "+f"(c[0]), "+f"(c[1]), "+f"(c[2]), "+f"(c[3])
        : "r"(a[0]), "r"(a[1]), "r"(a[2]), "r"(a[3]), "r"(b[0]), "r"(b[1]));
}

// ---------------- init ----------------
__global__ void __launch_bounds__(256) init_kernel(const int* __restrict__ dmask) {
    int b = blockIdx.x, tid = threadIdx.x;
    g_h[b*HH + tid] = 0.f;
    g_c[b*HH + tid] = 0.f;
    __shared__ int red[256];
    int s = 0;
    for (int m = tid; m < MM; m += 256) s += dmask[b*MM + m];
    red[tid] = s; __syncthreads();
    for (int st = 128; st; st >>= 1) { if (tid < st) red[tid] += red[tid + st]; __syncthreads(); }
    if (tid == 0) { g_si[b] = 0; g_ei[b] = red[0] - 1; g_len[b] = red[0]; g_ms[b] = 0; g_me[b] = 0; }
}

__global__ void prefix_kernel() {
    int t = threadIdx.x;
    int v = g_len[t];
    int x = v;
    #pragma unroll
    for (int o = 1; o < 32; o <<= 1) {
        int y = __shfl_up_sync(0xffffffffu, x, o);
        if (t >= o) x += y;
    }
    g_off[t] = x - v;
    if (t == 31) g_off[32] = x;
}

__global__ void __launch_bounds__(256) map_kernel() {
    int idx = blockIdx.x * 256 + threadIdx.x;
    int b = idx / MM, m = idx - b * MM;
    if (m < g_len[b]) {
        int cr = g_off[b] + m;
        g_rowb[cr] = b;
        g_rowm[cr] = m;
    }
}

// ---------------- bf16 split conversions ----------------
__device__ __forceinline__ void split2(float x, __nv_bfloat16& hi, __nv_bfloat16& lo) {
    hi = __float2bfloat16(x);
    lo = __float2bfloat16(x - __bfloat162float(hi));
}

__global__ void __launch_bounds__(256) convA3_kernel(const float* __restrict__ U) {
    int idx = blockIdx.x * 256 + threadIdx.x;
    int i = idx >> 9, c = idx & 511;
    int b = i / MM, m = i - b * MM;
    if (m >= g_len[b]) return;
    int crow = g_off[b] + m;
    __nv_bfloat16 hi, lo; split2(U[idx], hi, lo);
    size_t base = (size_t)crow * K1A;
    g_A3[base + c] = hi; g_A3[base + 512 + c] = lo; g_A3[base + 1024 + c] = hi;
}
__global__ void __launch_bounds__(256) convB3_kernel(const float* __restrict__ W, int which) {
    __nv_bfloat16* B3 = which ? g_B3e : g_B3s;
    int idx = blockIdx.x * 256 + threadIdx.x;
    int j = idx >> 9, c = idx & 511;
    __nv_bfloat16 hi, lo; split2(W[(size_t)j * 768 + c], hi, lo);
    size_t base = (size_t)j * K1A;
    B3[base + c] = hi; B3[base + 512 + c] = hi; B3[base + 1024 + c] = lo;
}
__global__ void __launch_bounds__(256) convW23_kernel(const float* __restrict__ W2, int which) {
    __nv_bfloat16* W23 = which ? g_W23e : g_W23s;
    int idx = blockIdx.x * 256 + threadIdx.x;
    int j = idx >> 8, c = idx & 255;
    __nv_bfloat16 hi, lo; split2(W2[(size_t)j * 256 + c], hi, lo);
    size_t base = (size_t)j * K2A;
    W23[base + c] = hi; W23[base + 256 + c] = hi; W23[base + 512 + c] = lo;
}

// ---------------- HMMA GEMM (R5 body), compact rows, skip stripes >= R ----------------
// mode 0: raw fp32 store. mode 1: bias + maxpool16 -> Cout[rows, 256].
__global__ void __launch_bounds__(256) gemm_hmma_kernel(
    const __nv_bfloat16* __restrict__ A, const __nv_bfloat16* __restrict__ Bw,
    float* __restrict__ Cout, const float* __restrict__ bias, int Ktot, int mode)
{
    int m0 = blockIdx.x * 128, n0 = blockIdx.y * 128;
    if (m0 >= g_off[BB]) return;

    __shared__ __align__(16) __nv_bfloat16 As[2][128][40];
    __shared__ __align__(16) __nv_bfloat16 Bs[2][128][40];
    int tid = threadIdx.x, lane = tid & 31, wid = tid >> 5;
    int wm = wid >> 2, wn = wid & 3;

    const int STG = 128 * 40 * 2;
    uint32_t sA = smem_u32(&As[0][0][0]);
    uint32_t sB = smem_u32(&Bs[0][0][0]);

    float acc[4][4][4];
    #pragma unroll
    for (int i = 0; i < 4; i++)
        #pragma unroll
        for (int j = 0; j < 4; j++)
            #pragma unroll
            for (int q = 0; q < 4; q++) acc[i][j][q] = 0.f;

    auto load_stage = [&](int c, int buf) {
        int kc = c * 32;
        #pragma unroll
        for (int i = 0; i < 2; i++) {
            int f = tid + i * 256;
            int r = f >> 2, q = f & 3;
            cp16(sA + buf * STG + r * 80 + q * 16, A + (size_t)(m0 + r) * Ktot + kc + q * 8);
        }
        #pragma unroll
        for (int i = 0; i < 2; i++) {
            int f = tid + i * 256;
            int r = f >> 2, q = f & 3;
            cp16(sB + buf * STG + r * 80 + q * 16, Bw + (size_t)(n0 + r) * Ktot + kc + q * 8);
        }
        asm volatile("cp.async.commit_group;" ::: "memory");
    };

    auto compute = [&](int buf) {
        #pragma unroll
        for (int ks = 0; ks < 2; ks++) {
            uint32_t a[4][4], b[4][2];
            #pragma unroll
            for (int mi = 0; mi < 4; mi++) {
                uint32_t addr = sA + buf * STG
                    + (wm * 64 + mi * 16 + (lane & 15)) * 80 + (ks * 16 + (lane >> 4) * 8) * 2;
                ldm_x4(a[mi], addr);
            }
            #pragma unroll
            for (int ni = 0; ni < 4; ni++) {
                uint32_t addr = sB + buf * STG
                    + (wn * 32 + ni * 8 + (lane & 7)) * 80 + (ks * 16 + ((lane >> 3) & 1) * 8) * 2;
                ldm_x2(b[ni], addr);
            }
            #pragma unroll
            for (int mi = 0; mi < 4; mi++)
                #pragma unroll
                for (int ni = 0; ni < 4; ni++)
                    mma16816(acc[mi][ni], a[mi], b[ni]);
        }
    };

    int NC = Ktot >> 5;
    load_stage(0, 0);
    for (int c = 0; c < NC; c++) {
        if (c + 1 < NC) {
            load_stage(c + 1, (c + 1) & 1);
            asm volatile("cp.async.wait_group 1;" ::: "memory");
        } else {
            asm volatile("cp.async.wait_group 0;" ::: "memory");
        }
        __syncthreads();
        compute(c & 1);
        __syncthreads();
    }

    int gr = lane >> 2, q = lane & 3;
    if (mode == 0) {
        #pragma unroll
        for (int mi = 0; mi < 4; mi++) {
            int row = m0 + wm * 64 + mi * 16 + gr;
            float* d0 = Cout + (size_t)row * HP + n0 + wn * 32;
            float* d1 = Cout + (size_t)(row + 8) * HP + n0 + wn * 32;
            #pragma unroll
            for (int ni = 0; ni < 4; ni++) {
                int colq = ni * 8 + q * 2;
                *(float2*)(d0 + colq) = make_float2(acc[mi][ni][0], acc[mi][ni][1]);
                *(float2*)(d1 + colq) = make_float2(acc[mi][ni][2], acc[mi][ni][3]);
            }
        }
    } else {
        float bv[2][2][2];
        #pragma unroll
        for (int g = 0; g < 2; g++)
            #pragma unroll
            for (int f2 = 0; f2 < 2; f2++)
                #pragma unroll
                for (int j = 0; j < 2; j++)
                    bv[g][f2][j] = __ldg(bias + n0 + wn * 32 + g * 16 + f2 * 8 + q * 2 + j);
        #pragma unroll
        for (int mi = 0; mi < 4; mi++) {
            int row = m0 + wm * 64 + mi * 16 + gr;
            #pragma unroll
            for (int g = 0; g < 2; g++) {
                float lo = -3.4e38f, hi = -3.4e38f;
                #pragma unroll
                for (int f2 = 0; f2 < 2; f2++) {
                    lo = fmaxf(lo, fmaxf(acc[mi][2*g + f2][0] + bv[g][f2][0],
                                         acc[mi][2*g + f2][1] + bv[g][f2][1]));
                    hi = fmaxf(hi, fmaxf(acc[mi][2*g + f2][2] + bv[g][f2][0],
                                         acc[mi][2*g + f2][3] + bv[g][f2][1]));
                }
                lo = fmaxf(lo, __shfl_xor_sync(0xffffffffu, lo, 1));
                lo = fmaxf(lo, __shfl_xor_sync(0xffffffffu, lo, 2));
                hi = fmaxf(hi, __shfl_xor_sync(0xffffffffu, hi, 1));
                hi = fmaxf(hi, __shfl_xor_sync(0xffffffffu, hi, 2));
                if (q == 0) {
                    int h = ((n0 + wn * 32) >> 4) + g;
                    Cout[(size_t)row * HH + h] = lo;
                    Cout[(size_t)(row + 8) * HH + h] = hi;
                }
            }
        }
    }
}

// ---------------- LSTM (warp per (b,j), double-buffered h/c) ----------------
__global__ void __launch_bounds__(256) lstm_kernel(const float* __restrict__ U,
        const float* __restrict__ Wih, const float* __restrict__ Whh,
        const float* __restrict__ bih, const float* __restrict__ bhh, int rb) {
    int w = blockIdx.x * 8 + (threadIdx.x >> 5);
    int b = w >> 8, j = w & 255, l = threadIdx.x & 31;
    const float4* us = (const float4*)(U + (size_t)(b * MM + g_si[b]) * H2);
    const float4* ue = (const float4*)(U + (size_t)(b * MM + g_ei[b]) * H2);
    const float4* hb = (const float4*)(g_h + rb * (BB * HH) + b * HH);
    float acc[4] = {0.f, 0.f, 0.f, 0.f};
    #pragma unroll
    for (int i = 0; i < 8; i++) {
        int k4 = l + 32 * i;
        float4 x = (k4 < 128) ? us[k4] : ue[k4 - 128];
        #pragma unroll
        for (int qg = 0; qg < 4; qg++) {
            float4 ww = ((const float4*)(Wih + (size_t)(qg * HH + j) * H4))[k4];
            acc[qg] += x.x * ww.x + x.y * ww.y + x.z * ww.z + x.w * ww.w;
        }
    }
    #pragma unroll
    for (int i = 0; i < 2; i++) {
        int k4 = l + 32 * i;
        float4 x = hb[k4];
        #pragma unroll
        for (int qg = 0; qg < 4; qg++) {
            float4 ww = ((const float4*)(Whh + (size_t)(qg * HH + j) * HH))[k4];
            acc[qg] += x.x * ww.x + x.y * ww.y + x.z * ww.z + x.w * ww.w;
        }
    }
    #pragma unroll
    for (int qg = 0; qg < 4; qg++)
        #pragma unroll
        for (int o = 16; o; o >>= 1) acc[qg] += __shfl_xor_sync(0xffffffffu, acc[qg], o);
    if (l == 0) {
        float gi = acc[0] + bih[j]        + bhh[j];
        float gf = acc[1] + bih[HH + j]   + bhh[HH + j];
        float gg = acc[2] + bih[2*HH + j] + bhh[2*HH + j];
        float go = acc[3] + bih[3*HH + j] + bhh[3*HH + j];
        float co = g_c[rb * (BB*HH) + b*HH + j];
        float cn = sigm(gf) * co + sigm(gi) * tanhf(gg);
        int wb = 1 - rb;
        g_c[wb * (BB*HH) + b*HH + j] = cn;
        g_h[wb * (BB*HH) + b*HH + j] = sigm(go) * tanhf(cn);
    }
}

// ---------------- r = tanh([h,u_s,u_e] @ Wlin^T)  (warp per (b,j)) ----------------
__global__ void __launch_bounds__(256) r_kernel(const float* __restrict__ U,
                                                const float* __restrict__ Wlin, int hbuf) {
    int w = blockIdx.x * 8 + (threadIdx.x >> 5);
    int b = w >> 8, j = w & 255, l = threadIdx.x & 31;
    const float4* hb = (const float4*)(g_h + hbuf * (BB * HH) + b * HH);
    const float4* us = (const float4*)(U + (size_t)(b * MM + g_si[b]) * H2);
    const float4* ue = (const float4*)(U + (size_t)(b * MM + g_ei[b]) * H2);
    const float4* wr = (const float4*)(Wlin + (size_t)j * H5);
    float acc = 0.f;
    #pragma unroll
    for (int i = 0; i < 10; i++) {
        int k4 = l + 32 * i;
        float4 x = (k4 < 64) ? hb[k4] : ((k4 < 192) ? us[k4 - 64] : ue[k4 - 192]);
        float4 ww = wr[k4];
        acc += x.x * ww.x + x.y * ww.y + x.z * ww.z + x.w * ww.w;
    }
    #pragma unroll
    for (int o = 16; o; o >>= 1) acc += __shfl_xor_sync(0xffffffffu, acc, o);
    if (l == 0) g_r[b * HH + j] = tanhf(acc);
}

// ---------------- addend[b][j] = b1[j] + r[b] . W1[j, 512:768] ----------------
__global__ void __launch_bounds__(256) addend_kernel(const float* __restrict__ Wm1,
                                                     const float* __restrict__ bm1) {
    __shared__ float sr[HH];
    int b = blockIdx.x, tid = threadIdx.x;
    for (int k = tid; k < HH; k += 256) sr[k] = g_r[b*HH + k];
    __syncthreads();
    int j = blockIdx.y * 256 + tid;
    const float* w = Wm1 + (size_t)j * 768 + 512;
    float acc = bm1[j];
    #pragma unroll 8
    for (int k = 0; k < HH; k += 4) {
        float4 x = *(const float4*)(sr + k);
        float4 a = *(const float4*)(w + k);
        acc += x.x * a.x + x.y * a.y + x.z * a.z + x.w * a.w;
    }
    g_add[b*HP + j] = acc;
}

// ---------------- phase1 (compact rows): m1 = maxpool16(CU + add) ----------------
__global__ void __launch_bounds__(256) phase1_kernel(int which) {
    const float* CU = which ? g_CU_e : g_CU_s;
    int R = g_off[BB];
    int crow0 = blockIdx.x * 8, tid = threadIdx.x;
    if (crow0 >= R) return;
    int j0 = tid * 16;
    #pragma unroll
    for (int rr = 0; rr < 8; rr++) {
        int crow = crow0 + rr;
        if (crow >= R) break;
        int b = g_rowb[crow];
        const float* ab = g_add + b * HP;
        const float* cu = CU + (size_t)crow * HP;
        float mx = -3.4e38f;
        #pragma unroll
        for (int qq = 0; qq < 4; qq++) {
            float4 v = *(const float4*)(cu + j0 + qq * 4);
            float4 a = __ldg((const float4*)(ab + j0 + qq * 4));
            mx = fmaxf(mx, fmaxf(fmaxf(v.x + a.x, v.y + a.y), fmaxf(v.z + a.z, v.w + a.w)));
        }
        g_m1[(size_t)crow * HH + tid] = mx;
        __nv_bfloat16 hi, lo; split2(mx, hi, lo);
        g_m3[(size_t)crow * K2A + tid] = hi;
        g_m3[(size_t)crow * K2A + 256 + tid] = lo;
        g_m3[(size_t)crow * K2A + 512 + tid] = hi;
    }
}

// ---------------- phase3 (compact rows): alpha = max_p([m1,m2] . W12[p] + b12[p]) ----------------
__global__ void __launch_bounds__(256) alpha_kernel(const float* __restrict__ W12,
                                                    const float* __restrict__ b12) {
    __shared__ float w12T[512 * 17];
    int R = g_off[BB];
    int crow0 = blockIdx.x * 8;
    if (crow0 >= R) return;
    int tid = threadIdx.x, wid = tid >> 5, l = tid & 31;
    for (int idx = tid; idx < 8192; idx += 256) {
        int p = idx >> 9, k = idx & 511;
        w12T[k * 17 + p] = W12[idx];
    }
    __syncthreads();
    int crow = crow0 + wid;
    if (crow < R) {
        float acc[16];
        #pragma unroll
        for (int p = 0; p < 16; p++) acc[p] = 0.f;
        #pragma unroll
        for (int i = 0; i < 16; i++) {
            int k = i * 32 + l;
            float a = (k < 256) ? g_m1[(size_t)crow * HH + k] : g_m2[(size_t)crow * HH + (k - 256)];
            const float* wr = w12T + k * 17;
            #pragma unroll
            for (int p = 0; p < 16; p++) acc[p] += a * wr[p];
        }
        #pragma unroll
        for (int p = 0; p < 16; p++)
            #pragma unroll
            for (int o = 16; o; o >>= 1) acc[p] += __shfl_xor_sync(0xffffffffu, acc[p], o);
        if (l == 0) {
            float mx = -3.4e38f;
            #pragma unroll
            for (int p = 0; p < 16; p++) mx = fmaxf(mx, acc[p] + __ldg(b12 + p));
            int b = g_rowb[crow], m = g_rowm[crow];
            g_alpha[b * MM + m] = mx;
        }
    }
}

// ---------------- argmax + logsumexp + state update ----------------
__global__ void __launch_bounds__(256) select_kernel(const int* __restrict__ dmask,
                                                     const int* __restrict__ span,
                                                     int t, int isEnd) {
    __shared__ float sv[256];
    __shared__ int   sidx[256];
    __shared__ float red[256];
    int b = blockIdx.x, tid = threadIdx.x;
    const float* al = g_alpha + b * MM;
    const int* dm = dmask + b * MM;

    float best = -3.4e38f; int bi = 0;
    for (int m = tid; m < MM; m += 256) {
        float v = al[m] + (dm[m] ? 0.f : -1e30f);
        if (v > best) { best = v; bi = m; }
    }
    sv[tid] = best; sidx[tid] = bi; __syncthreads();
    for (int s = 128; s; s >>= 1) {
        if (tid < s) {
            float ov = sv[tid + s]; int oi = sidx[tid + s];
            if (ov > sv[tid] || (ov == sv[tid] && oi < sidx[tid])) { sv[tid] = ov; sidx[tid] = oi; }
        }
        __syncthreads();
    }
    float mx = sv[0]; int amax = sidx[0];
    __syncthreads();

    float ssum = 0.f;
    for (int m = tid; m < MM; m += 256) {
        float v = al[m] + (dm[m] ? 0.f : -1e30f);
        ssum += expf(v - mx);
    }
    red[tid] = ssum; __syncthreads();
    for (int s = 128; s; s >>= 1) { if (tid < s) red[tid] += red[tid + s]; __syncthreads(); }

    if (tid == 0) {
        float lse = mx + logf(red[0]);
        int tgt = span[b * 2 + isEnd];
        float vt = al[tgt] + (dm[tgt] ? 0.f : -1e30f);
        float lterm = -(vt - lse);
        int* idxArr = isEnd ? g_ei : g_si;
        int* mArr   = isEnd ? g_me : g_ms;
        int idx = amax, mnew;
        if (t == 0) mnew = 1;
        else {
            int mo = mArr[b];
            int prev = idxArr[b] * mo;
            idx = idx * mo;
            mnew = (idx != prev) ? 1 : 0;
        }
        mArr[b] = mnew; idxArr[b] = idx;
        (isEnd ? g_res_e  : g_res_s )[t*BB + b] = idx;
        (isEnd ? g_resme  : g_resms )[t*BB + b] = mnew;
        (isEnd ? g_lterm_e: g_lterm_s)[t*BB + b] = lterm;
    }
}

// ---------------- finalize ----------------
__global__ void __launch_bounds__(64) finish_kernel(float* __restrict__ out) {
    __shared__ float Ls[TT], Le[TT];
    int tid = threadIdx.x;
    if (tid < 2 * TT) {
        int t = tid & 3;
        const float* src = (tid < TT) ? g_lterm_s : g_lterm_e;
        float s = 0.f;
        for (int b = 0; b < BB; b++) s += src[t*BB + b];
        if (tid < TT) Ls[t] = s / (float)BB; else Le[t] = s / (float)BB;
    }
    __syncthreads();
    if (tid < 32) {
        int b = tid;
        float acc = 0.f;
        for (int t = 0; t < TT; t++)
            acc += Ls[t] * (float)g_resms[t*BB + b] + Le[t] * (float)g_resme[t*BB + b];
        acc /= (float)TT;
        float tot = acc;
        #pragma unroll
        for (int o = 16; o; o >>= 1) tot += __shfl_xor_sync(0xffffffffu, tot, o);
        if (b == 0) out[0] = tot / (float)BB;
        int ps = 0, pe = 0;
        for (int t = 0; t < TT; t++) { ps += g_resms[t*BB + b]; pe += g_resme[t*BB + b]; }
        out[1 + b]  = (float)g_res_s[(ps - 1)*BB + b];
        out[33 + b] = (float)g_res_e[(pe - 1)*BB + b];
    }
}

// ---------------- host ----------------
extern "C" void kernel_launch(void* const* d_in, const int* in_sizes, int n_in,
                              void* d_out, int out_size) {
    const float* U      = (const float*)d_in[0];
    const int*   dmask  = (const int*)  d_in[1];
    const int*   span   = (const int*)  d_in[2];
    const float* Wih    = (const float*)d_in[3];
    const float* Whh    = (const float*)d_in[4];
    const float* bih    = (const float*)d_in[5];
    const float* bhh    = (const float*)d_in[6];
    const float* Ws_lin = (const float*)d_in[7];
    const float* Ws_m1  = (const float*)d_in[8];
    const float* bs_m1  = (const float*)d_in[9];
    const float* Ws_m2  = (const float*)d_in[10];
    const float* bs_m2  = (const float*)d_in[11];
    const float* Ws_m12 = (const float*)d_in[12];
    const float* bs_m12 = (const float*)d_in[13];
    const float* We_lin = (const float*)d_in[14];
    const float* We_m1  = (const float*)d_in[15];
    const float* be_m1  = (const float*)d_in[16];
    const float* We_m2  = (const float*)d_in[17];
    const float* be_m2  = (const float*)d_in[18];
    const float* We_m12 = (const float*)d_in[19];
    const float* be_m12 = (const float*)d_in[20];
    float* out = (float*)d_out;

    float *CU_s, *CU_e, *m2p;
    cudaGetSymbolAddress((void**)&CU_s, g_CU_s);
    cudaGetSymbolAddress((void**)&CU_e, g_CU_e);
    cudaGetSymbolAddress((void**)&m2p, g_m2);
    __nv_bfloat16 *A3, *B3s, *B3e, *W23s, *W23e, *m3;
    cudaGetSymbolAddress((void**)&A3, g_A3);
    cudaGetSymbolAddress((void**)&B3s, g_B3s);
    cudaGetSymbolAddress((void**)&B3e, g_B3e);
    cudaGetSymbolAddress((void**)&W23s, g_W23s);
    cudaGetSymbolAddress((void**)&W23e, g_W23e);
    cudaGetSymbolAddress((void**)&m3, g_m3);

    init_kernel<<<BB, 256>>>(dmask);
    prefix_kernel<<<1, 32>>>();
    map_kernel<<<MTOT/256, 256>>>();

    convA3_kernel<<<(MTOT*512)/256, 256>>>(U);
    convB3_kernel<<<(HP*512)/256, 256>>>(Ws_m1, 0);
    convB3_kernel<<<(HP*512)/256, 256>>>(We_m1, 1);
    convW23_kernel<<<(HP*256)/256, 256>>>(Ws_m2, 0);
    convW23_kernel<<<(HP*256)/256, 256>>>(We_m2, 1);

    dim3 ggrid(MTOT / 128, HP / 128);   // (150, 32), stripes >= R exit early
    gemm_hmma_kernel<<<ggrid, 256>>>(A3, B3s, CU_s, nullptr, K1A, 0);
    gemm_hmma_kernel<<<ggrid, 256>>>(A3, B3e, CU_e, nullptr, K1A, 0);

    for (int t = 0; t < TT; t++) {
        int rb = t & 1, wb = 1 - rb;
        lstm_kernel<<<1024, 256>>>(U, Wih, Whh, bih, bhh, rb);

        // ---- start pointer ----
        r_kernel<<<1024, 256>>>(U, Ws_lin, wb);
        addend_kernel<<<dim3(BB, 16), 256>>>(Ws_m1, bs_m1);
        phase1_kernel<<<MTOT/8, 256>>>(0);
        gemm_hmma_kernel<<<ggrid, 256>>>(m3, W23s, m2p, bs_m2, K2A, 1);
        alpha_kernel<<<MTOT/8, 256>>>(Ws_m12, bs_m12);
        select_kernel<<<BB, 256>>>(dmask, span, t, 0);

        // ---- end pointer (updated s_i, pre-update e_i) ----
        r_kernel<<<1024, 256>>>(U, We_lin, wb);
        addend_kernel<<<dim3(BB, 16), 256>>>(We_m1, be_m1);
        phase1_kernel<<<MTOT/8, 256>>>(1);
        gemm_hmma_kernel<<<ggrid, 256>>>(m3, W23e, m2p, be_m2, K2A, 1);
        alpha_kernel<<<MTOT/8, 256>>>(We_m12, be_m12);
        select_kernel<<<BB, 256>>>(dmask, span, t, 1);
    }

    finish_kernel<<<1, 64>>>(out);
}